// round 15
// baseline (speedup 1.0000x reference)
#include <cuda_runtime.h>
#include <cuda_fp16.h>
#include <cstdint>

#define D_MODEL 4096
#define N_TOK   8192
#define CTRL_PER_LAYER 4194304u   /* 32 ntiles * 64 ktiles * 2048 u32 */

__device__ __half    g_ah[(size_t)N_TOK * D_MODEL];     // fp16 activations
__device__ __half    g_yh[(size_t)N_TOK * D_MODEL];     // fp16 intermediate y
__device__ uint32_t  g_bctl[3][CTRL_PER_LAYER];         // PRMT control words
__device__ double    g_part[3072];
__device__ float     g_scale3[3];

static __device__ __forceinline__ uint32_t smem_u32(const void* p) {
    uint32_t r;
    asm("{ .reg .u64 t; cvta.to.shared.u64 t, %1; cvt.u32.u64 %0, t; }" : "=r"(r) : "l"(p));
    return r;
}
#define CP16(dst, ptr) do { \
    unsigned long long g_ = __cvta_generic_to_global((const void*)(ptr)); \
    asm volatile("cp.async.cg.shared.global [%0], [%1], 16;" :: "r"(dst), "l"(g_)); } while (0)
#define CP_COMMIT() asm volatile("cp.async.commit_group;")
#define CP_WAIT(n)  asm volatile("cp.async.wait_group %0;" :: "n"(n))

static __device__ __forceinline__ void ldsm4(uint32_t a[4], uint32_t addr) {
    asm volatile("ldmatrix.sync.aligned.m8n8.x4.shared.b16 {%0,%1,%2,%3}, [%4];"
                 : "=r"(a[0]), "=r"(a[1]), "=r"(a[2]), "=r"(a[3]) : "r"(addr));
}
static __device__ __forceinline__ void mma16816(float c[4], const uint32_t a[4], const uint32_t* b) {
    asm volatile("mma.sync.aligned.m16n8k16.row.col.f32.f16.f16.f32 "
                 "{%0,%1,%2,%3}, {%4,%5,%6,%7}, {%8,%9}, {%0,%1,%2,%3};"
                 : "+f"(c[0]), "+f"(c[1]), "+f"(c[2]), "+f"(c[3])
                 : "r"(a[0]), "r"(a[1]), "r"(a[2]), "r"(a[3]), "r"(b[0]), "r"(b[1]));
}
// byte pool: byte0=0x00, byte1=0x3C(+1 hi), byte2=0xBC(-1 hi), byte3=0x00
static __device__ __forceinline__ uint32_t wprmt(uint32_t ctrl) {
    uint32_t d;
    asm("prmt.b32 %0, %1, %1, %2;" : "=r"(d) : "r"(0x00BC3C00u), "r"(ctrl));
    return d;
}
static __device__ __forceinline__ uint32_t lds32(uint32_t addr) {
    uint32_t d;
    asm volatile("ld.shared.u32 %0, [%1];" : "=r"(d) : "r"(addr));
    return d;
}

// ---- abs-mean of |W| in fp64, all 3 layers ----
__global__ void __launch_bounds__(256) absmean_part3(const float* __restrict__ w0,
                                                     const float* __restrict__ w1,
                                                     const float* __restrict__ w2) {
    int wsel = blockIdx.x >> 10;
    const float* w = (wsel == 0) ? w0 : (wsel == 1) ? w1 : w2;
    int b = blockIdx.x & 1023;
    double s = 0.0;
    for (int i = b * 256 + threadIdx.x; i < D_MODEL * D_MODEL; i += 1024 * 256)
        s += (double)fabsf(w[i]);
    __shared__ double rd[256];
    rd[threadIdx.x] = s; __syncthreads();
    for (int o = 128; o > 0; o >>= 1) { if (threadIdx.x < o) rd[threadIdx.x] += rd[threadIdx.x + o]; __syncthreads(); }
    if (threadIdx.x == 0) g_part[blockIdx.x] = rd[0];
}
__global__ void __launch_bounds__(256) absmean_fin3() {
    int t = threadIdx.x, base = blockIdx.x << 10;
    __shared__ double rd[256];
    rd[t] = g_part[base + t] + g_part[base + t + 256] + g_part[base + t + 512] + g_part[base + t + 768];
    __syncthreads();
    for (int o = 128; o > 0; o >>= 1) { if (t < o) rd[t] += rd[t + o]; __syncthreads(); }
    if (t == 0) g_scale3[blockIdx.x] = (float)(rd[0] / 16777216.0 + 1e-8);
}

// ---- ternarize -> PRMT control words in B-fragment order ----
// ctrl u32 for (ntile, ktile, kk, nh, n8, lane): reg r in {0,1}, parity p in {0,1}
//   n = ntile*128 + nh*64 + n8*8 + (lane>>2)
//   k = ktile*64 + kk*16 + r*8 + (lane&3)*2 + p
//   sel: +1 -> 1 (0x3C), -1 -> 2 (0xBC), 0 -> 0
//   ctrl |= sel << (r*16 + 4 + p*8)
__global__ void __launch_bounds__(256) quantb3(const float* __restrict__ w0,
                                               const float* __restrict__ w1,
                                               const float* __restrict__ w2) {
    int wsel = blockIdx.x >> 10;
    const float* w = (wsel == 0) ? w0 : (wsel == 1) ? w1 : w2;
    uint32_t* outp = g_bctl[wsel];
    const float s = g_scale3[wsel];
    int b = blockIdx.x & 1023;
    for (uint32_t g = b * 256 + threadIdx.x; g < CTRL_PER_LAYER; g += 1024 * 256) {
        uint32_t nt = g >> 17;
        uint32_t kt = (g >> 11) & 63u;
        uint32_t idx = g & 2047u;
        uint32_t kk = idx >> 9, nh = (idx >> 8) & 1u, n8 = (idx >> 5) & 7u, lane = idx & 31u;
        uint32_t n = nt * 128u + nh * 64u + n8 * 8u + (lane >> 2);
        uint32_t kb = kt * 64u + kk * 16u + (lane & 3u) * 2u;
        uint32_t ctrl = 0;
#pragma unroll
        for (int r = 0; r < 2; r++)
#pragma unroll
            for (int p = 0; p < 2; p++) {
                float wv = w[(size_t)n * D_MODEL + kb + r * 8 + p];
                float q = fminf(fmaxf(rintf(wv / s), -1.f), 1.f);
                uint32_t sel = (q > 0.5f) ? 1u : (q < -0.5f) ? 2u : 0u;
                ctrl |= sel << (r * 16 + 4 + p * 8);
            }
        outp[g] = ctrl;
    }
}

// ---- act: RMSNorm -> SiLU -> fp16 (reads fp32 x first layer, fp16 y after) ----
__global__ void __launch_bounds__(256) act_kernel(const float* __restrict__ xin, int first) {
    int row = blockIdx.x, t = threadIdx.x;
    float h[16]; float ss = 0.f;
    if (first) {
        const float4* rp = (const float4*)(xin + (size_t)row * D_MODEL);
#pragma unroll
        for (int i = 0; i < 4; i++) {
            float4 v = rp[t + (i << 8)];
            h[4*i] = v.x; h[4*i+1] = v.y; h[4*i+2] = v.z; h[4*i+3] = v.w;
            ss += v.x*v.x + v.y*v.y + v.z*v.z + v.w*v.w;
        }
    } else {
        const uint4* rp = (const uint4*)(g_yh + (size_t)row * D_MODEL);
#pragma unroll
        for (int i = 0; i < 2; i++) {
            uint4 u = rp[t + (i << 8)];
            uint32_t uu[4] = {u.x, u.y, u.z, u.w};
#pragma unroll
            for (int q = 0; q < 4; q++) {
                __half2 hv = *(__half2*)&uu[q];
                float a = __half2float(hv.x), b2 = __half2float(hv.y);
                h[8*i + 2*q] = a; h[8*i + 2*q + 1] = b2;
                ss += a*a + b2*b2;
            }
        }
    }
    __shared__ float red[256];
    red[t] = ss; __syncthreads();
#pragma unroll
    for (int o = 128; o > 0; o >>= 1) { if (t < o) red[t] += red[t + o]; __syncthreads(); }
    float rs = rsqrtf(red[0] * (1.0f / 4096.0f) + 1.1920929e-7f);
#pragma unroll
    for (int e = 0; e < 16; e++) {
        float v = h[e] * rs;
        h[e] = v / (1.0f + expf(-v));
    }
    __half2* hp = (__half2*)(g_ah + (size_t)row * D_MODEL);
    if (first) {
#pragma unroll
        for (int i = 0; i < 4; i++) {
            int base = (t + (i << 8)) * 2;
            hp[base]     = __floats2half2_rn(h[4*i],   h[4*i+1]);
            hp[base + 1] = __floats2half2_rn(h[4*i+2], h[4*i+3]);
        }
    } else {
#pragma unroll
        for (int i = 0; i < 2; i++) {
            int base = (t + (i << 8)) * 4;
#pragma unroll
            for (int q = 0; q < 4; q++)
                hp[base + q] = __floats2half2_rn(h[8*i + 2*q], h[8*i + 2*q + 1]);
        }
    }
}

// ---- GEMM: CTA 256Mx128N, 256 thr, warp 64x64, 4 stages, PRMT-decoded B ----
#define STAGES 4
#define A_BYTES 32768u
#define B_BYTES 8192u
#define STAGE_BYTES (A_BYTES + B_BYTES)
#define SMEM_TOTAL (1024 + STAGES * STAGE_BYTES)

__global__ void __launch_bounds__(256, 1) gemm_kernel(int layer, int last, float* __restrict__ dout) {
    extern __shared__ char smraw[];
    uint32_t sb = smem_u32(smraw);
    uint32_t stg = (sb + 1023u) & ~1023u;
    const __half* __restrict__ Ah = g_ah;

    int tid = threadIdx.x, bid = blockIdx.x;
    int mt = ((bid >> 8) << 3) | (bid & 7);
    int nt = (bid >> 3) & 31;
    int m0 = mt << 8, n0 = nt << 7;
    const uint32_t* __restrict__ BcCTA = g_bctl[layer] + (uint32_t)nt * 131072u;

    // A fill: 8 chunks/thread (256 rows x 128B, SW128)
    uint32_t sA[8]; uint32_t gA[8];
#pragma unroll
    for (int i = 0; i < 8; i++) {
        uint32_t q = (uint32_t)tid + ((uint32_t)i << 8), r = q >> 3, c = q & 7u;
        uint32_t bo = r * 128u + c * 16u;
        sA[i] = bo ^ ((bo >> 3) & 0x70);
        gA[i] = ((uint32_t)m0 + r) * (uint32_t)D_MODEL + c * 8u;
    }
#define LOAD_STAGE(s_, kt_) do { \
    uint32_t st_ = stg + (uint32_t)(s_) * STAGE_BYTES; \
    uint32_t k0_ = (uint32_t)(kt_) * 64u; \
    _Pragma("unroll") \
    for (int i_ = 0; i_ < 8; i_++) CP16(st_ + sA[i_], Ah + gA[i_] + k0_); \
    CP16(st_ + A_BYTES + (uint32_t)tid * 16u,          BcCTA + (uint32_t)(kt_) * 2048u + tid * 4); \
    CP16(st_ + A_BYTES + 4096u + (uint32_t)tid * 16u,  BcCTA + (uint32_t)(kt_) * 2048u + 1024 + tid * 4); \
} while (0)

    int wid = tid >> 5, lane = tid & 31;
    int wm = (wid & 3) << 6;    // 4 M-warps x 64
    uint32_t nh = (uint32_t)(wid >> 2);  // 2 N-warps x 64

    float acc[4][8][4];
#pragma unroll
    for (int a = 0; a < 4; a++)
#pragma unroll
        for (int b = 0; b < 8; b++)
#pragma unroll
            for (int c = 0; c < 4; c++) acc[a][b][c] = 0.f;

    uint32_t aRow[4], aX[4];
    uint32_t koffA = ((lane >> 4) & 1) * 16;
#pragma unroll
    for (int i = 0; i < 4; i++) {
        uint32_t ra = wm + i * 16 + (lane & 15);
        aRow[i] = ra * 128u; aX[i] = (ra & 7u) << 4;
    }

    const int KT = D_MODEL / 64;   // 64 iterations
    for (int j = 0; j < STAGES - 1; j++) { LOAD_STAGE(j, j); CP_COMMIT(); }

    for (int j = 0; j < KT; j++) {
        CP_WAIT(2);
        __syncthreads();
        int jn = j + 3;
        if (jn < KT) LOAD_STAGE(jn & 3, jn);   // stage consumed at j-1; safe after sync
        CP_COMMIT();

        uint32_t aB = stg + (uint32_t)(j & 3) * STAGE_BYTES;
        uint32_t bB = aB + A_BYTES;
#pragma unroll
        for (int kk = 0; kk < 4; kk++) {
            uint32_t bfr[8][2];
            uint32_t bbase = bB + (((uint32_t)kk * 2u + nh) * 8u) * 128u + (uint32_t)lane * 4u;
#pragma unroll
            for (int ni = 0; ni < 8; ni++) {
                uint32_t ctrl = lds32(bbase + (uint32_t)ni * 128u);
                bfr[ni][0] = wprmt(ctrl);
                bfr[ni][1] = wprmt(ctrl >> 16);
            }
            uint32_t kb = (uint32_t)kk * 32u;
#pragma unroll
            for (int mi = 0; mi < 4; mi++) {
                uint32_t afr[4];
                ldsm4(afr, aB + aRow[mi] + ((kb + koffA) ^ aX[mi]));
#pragma unroll
                for (int ni = 0; ni < 8; ni++)
                    mma16816(acc[mi][ni], afr, bfr[ni]);
            }
        }
    }
    CP_WAIT(0);

    int g = lane >> 2, t4 = lane & 3;
    if (last) {
#pragma unroll
        for (int mi = 0; mi < 4; mi++) {
            size_t r0 = (size_t)(m0 + wm + mi * 16 + g);
#pragma unroll
            for (int ni = 0; ni < 8; ni++) {
                int col = n0 + (int)nh * 64 + ni * 8 + t4 * 2;
                *(float2*)(dout + r0 * D_MODEL + col)       = make_float2(acc[mi][ni][0], acc[mi][ni][1]);
                *(float2*)(dout + (r0 + 8) * D_MODEL + col) = make_float2(acc[mi][ni][2], acc[mi][ni][3]);
            }
        }
    } else {
        __half* yh = g_yh;
#pragma unroll
        for (int mi = 0; mi < 4; mi++) {
            size_t r0 = (size_t)(m0 + wm + mi * 16 + g);
#pragma unroll
            for (int ni = 0; ni < 8; ni++) {
                int col = n0 + (int)nh * 64 + ni * 8 + t4 * 2;
                *(__half2*)(yh + r0 * D_MODEL + col)       = __floats2half2_rn(acc[mi][ni][0], acc[mi][ni][1]);
                *(__half2*)(yh + (r0 + 8) * D_MODEL + col) = __floats2half2_rn(acc[mi][ni][2], acc[mi][ni][3]);
            }
        }
    }
}

extern "C" void kernel_launch(void* const* d_in, const int* in_sizes, int n_in,
                              void* d_out, int out_size) {
    const float* x  = (const float*)d_in[0];
    const float* w0 = (const float*)d_in[1];
    const float* w1 = (const float*)d_in[2];
    const float* w2 = (const float*)d_in[3];
    cudaFuncSetAttribute(gemm_kernel, cudaFuncAttributeMaxDynamicSharedMemorySize, SMEM_TOTAL);
    absmean_part3<<<3072, 256>>>(w0, w1, w2);
    absmean_fin3<<<3, 256>>>();
    quantb3<<<3072, 256>>>(w0, w1, w2);
    for (int l = 0; l < 3; l++) {
        act_kernel<<<N_TOK, 256>>>(x, l == 0);
        gemm_kernel<<<1024, 256, SMEM_TOTAL>>>(l, l == 2, (float*)d_out);
    }
}

// round 16
// speedup vs baseline: 1.1366x; 1.1366x over previous
#include <cuda_runtime.h>
#include <cuda_fp16.h>
#include <cstdint>

#define D_MODEL 4096
#define N_TOK   8192

__device__ __half  g_ah[(size_t)N_TOK * D_MODEL];       // fp16 activations
__device__ __half  g_yh[(size_t)N_TOK * D_MODEL];       // fp16 intermediate y
__device__ __half  g_wq[3][(size_t)D_MODEL * D_MODEL];  // fp16 ternary weights
__device__ double  g_part[3072];
__device__ float   g_scale3[3];

static __device__ __forceinline__ uint32_t smem_u32(const void* p) {
    uint32_t r;
    asm("{ .reg .u64 t; cvta.to.shared.u64 t, %1; cvt.u32.u64 %0, t; }" : "=r"(r) : "l"(p));
    return r;
}
#define CP16(dst, ptr) do { \
    unsigned long long g_ = __cvta_generic_to_global((const void*)(ptr)); \
    asm volatile("cp.async.cg.shared.global [%0], [%1], 16;" :: "r"(dst), "l"(g_)); } while (0)
#define CP_COMMIT() asm volatile("cp.async.commit_group;")
#define CP_WAIT(n)  asm volatile("cp.async.wait_group %0;" :: "n"(n))

static __device__ __forceinline__ void ldsm4(uint32_t a[4], uint32_t addr) {
    asm volatile("ldmatrix.sync.aligned.m8n8.x4.shared.b16 {%0,%1,%2,%3}, [%4];"
                 : "=r"(a[0]), "=r"(a[1]), "=r"(a[2]), "=r"(a[3]) : "r"(addr));
}
static __device__ __forceinline__ void mma16816(float c[4], const uint32_t a[4], const uint32_t* b) {
    asm volatile("mma.sync.aligned.m16n8k16.row.col.f32.f16.f16.f32 "
                 "{%0,%1,%2,%3}, {%4,%5,%6,%7}, {%8,%9}, {%0,%1,%2,%3};"
                 : "+f"(c[0]), "+f"(c[1]), "+f"(c[2]), "+f"(c[3])
                 : "r"(a[0]), "r"(a[1]), "r"(a[2]), "r"(a[3]), "r"(b[0]), "r"(b[1]));
}

// ---- weight prologue: abs-mean (fp64) + ternarize -> fp16, all 3 layers ----
__global__ void __launch_bounds__(256) absmean_part3(const float* __restrict__ w0,
                                                     const float* __restrict__ w1,
                                                     const float* __restrict__ w2) {
    int wsel = blockIdx.x >> 10;
    const float* w = (wsel == 0) ? w0 : (wsel == 1) ? w1 : w2;
    int b = blockIdx.x & 1023;
    double s = 0.0;
    for (int i = b * 256 + threadIdx.x; i < D_MODEL * D_MODEL; i += 1024 * 256)
        s += (double)fabsf(w[i]);
    __shared__ double rd[256];
    rd[threadIdx.x] = s; __syncthreads();
    for (int o = 128; o > 0; o >>= 1) { if (threadIdx.x < o) rd[threadIdx.x] += rd[threadIdx.x + o]; __syncthreads(); }
    if (threadIdx.x == 0) g_part[blockIdx.x] = rd[0];
}
__global__ void __launch_bounds__(256) absmean_fin3() {
    int t = threadIdx.x, base = blockIdx.x << 10;
    __shared__ double rd[256];
    rd[t] = g_part[base + t] + g_part[base + t + 256] + g_part[base + t + 512] + g_part[base + t + 768];
    __syncthreads();
    for (int o = 128; o > 0; o >>= 1) { if (t < o) rd[t] += rd[t + o]; __syncthreads(); }
    if (t == 0) g_scale3[blockIdx.x] = (float)(rd[0] / 16777216.0 + 1e-8);
}
__global__ void __launch_bounds__(256) quant3(const float* __restrict__ w0,
                                              const float* __restrict__ w1,
                                              const float* __restrict__ w2) {
    int wsel = blockIdx.x >> 11;
    const float* w = (wsel == 0) ? w0 : (wsel == 1) ? w1 : w2;
    __half2* outp = (__half2*)g_wq[wsel];
    const float s = g_scale3[wsel];
    int b = blockIdx.x & 2047;
    for (int i = b * 256 + threadIdx.x; i < (D_MODEL * D_MODEL) / 4; i += 2048 * 256) {
        float4 wv = ((const float4*)w)[i];
        __half2 a, c;
        a.x = __float2half_rn(fminf(fmaxf(rintf(wv.x / s), -1.f), 1.f));
        a.y = __float2half_rn(fminf(fmaxf(rintf(wv.y / s), -1.f), 1.f));
        c.x = __float2half_rn(fminf(fmaxf(rintf(wv.z / s), -1.f), 1.f));
        c.y = __float2half_rn(fminf(fmaxf(rintf(wv.w / s), -1.f), 1.f));
        outp[2 * i] = a;
        outp[2 * i + 1] = c;
    }
}

// ---- act: RMSNorm -> SiLU -> fp16 (fp32 x first layer, fp16 y after) ----
__global__ void __launch_bounds__(256) act_kernel(const float* __restrict__ xin, int first) {
    int row = blockIdx.x, t = threadIdx.x;
    float h[16]; float ss = 0.f;
    if (first) {
        const float4* rp = (const float4*)(xin + (size_t)row * D_MODEL);
#pragma unroll
        for (int i = 0; i < 4; i++) {
            float4 v = rp[t + (i << 8)];
            h[4*i] = v.x; h[4*i+1] = v.y; h[4*i+2] = v.z; h[4*i+3] = v.w;
            ss += v.x*v.x + v.y*v.y + v.z*v.z + v.w*v.w;
        }
    } else {
        const uint4* rp = (const uint4*)(g_yh + (size_t)row * D_MODEL);
#pragma unroll
        for (int i = 0; i < 2; i++) {
            uint4 u = rp[t + (i << 8)];
            uint32_t uu[4] = {u.x, u.y, u.z, u.w};
#pragma unroll
            for (int q = 0; q < 4; q++) {
                __half2 hv = *(__half2*)&uu[q];
                float a = __half2float(hv.x), b2 = __half2float(hv.y);
                h[8*i + 2*q] = a; h[8*i + 2*q + 1] = b2;
                ss += a*a + b2*b2;
            }
        }
    }
    __shared__ float red[256];
    red[t] = ss; __syncthreads();
#pragma unroll
    for (int o = 128; o > 0; o >>= 1) { if (t < o) red[t] += red[t + o]; __syncthreads(); }
    float rs = rsqrtf(red[0] * (1.0f / 4096.0f) + 1.1920929e-7f);
#pragma unroll
    for (int e = 0; e < 16; e++) {
        float v = h[e] * rs;
        h[e] = v / (1.0f + expf(-v));
    }
    __half2* hp = (__half2*)(g_ah + (size_t)row * D_MODEL);
    if (first) {
#pragma unroll
        for (int i = 0; i < 4; i++) {
            int base = (t + (i << 8)) * 2;
            hp[base]     = __floats2half2_rn(h[4*i],   h[4*i+1]);
            hp[base + 1] = __floats2half2_rn(h[4*i+2], h[4*i+3]);
        }
    } else {
#pragma unroll
        for (int i = 0; i < 2; i++) {
            int base = (t + (i << 8)) * 4;
#pragma unroll
            for (int q = 0; q < 4; q++)
                hp[base + q] = __floats2half2_rn(h[8*i + 2*q], h[8*i + 2*q + 1]);
        }
    }
}

// ---- GEMM: fp16 single-pass, CTA 128x128, 256 thr, 3 stages (97KB -> 2 CTAs/SM) ----
#define STAGES 3
#define STAGE_BYTES 32768u
#define SMEM_TOTAL (1024 + STAGES * STAGE_BYTES)

__global__ void __launch_bounds__(256, 2) gemm_kernel(int layer, int last, float* __restrict__ dout) {
    extern __shared__ char smraw[];
    uint32_t sb = smem_u32(smraw);
    uint32_t stg = (sb + 1023u) & ~1023u;
    const __half* __restrict__ Ah = g_ah;
    const __half* __restrict__ Wq = g_wq[layer];

    int tid = threadIdx.x, bid = blockIdx.x;
    int group = bid >> 8, rem = bid & 255;
    uint32_t m0 = (uint32_t)((group << 3) + (rem & 7)) << 7;
    uint32_t n0 = (uint32_t)(rem >> 3) << 7;

    uint32_t soff[4], aofs[4], bofs[4];
#pragma unroll
    for (int i = 0; i < 4; i++) {
        uint32_t q = (uint32_t)tid + ((uint32_t)i << 8), r = q >> 3, c = q & 7u;
        uint32_t bo = r * 128u + c * 16u;
        soff[i] = bo ^ ((bo >> 3) & 0x70);
        aofs[i] = (m0 + r) * (uint32_t)D_MODEL + c * 8u;
        bofs[i] = (n0 + r) * (uint32_t)D_MODEL + c * 8u;
    }
#define LOAD_STAGE(s_, kt_) do { \
    uint32_t st_ = stg + (uint32_t)(s_) * STAGE_BYTES; \
    uint32_t k0_ = (uint32_t)(kt_) * 64u; \
    _Pragma("unroll") \
    for (int i_ = 0; i_ < 4; i_++) { \
        CP16(st_ + soff[i_],           Ah + aofs[i_] + k0_); \
        CP16(st_ + 16384u + soff[i_],  Wq + bofs[i_] + k0_); \
    } } while (0)

    int wid = tid >> 5, lane = tid & 31;
    int wm = (wid & 1) << 6;   // 2 M-warps x 64
    int wn = (wid >> 1) << 5;  // 4 N-warps x 32

    float acc[4][4][4];
#pragma unroll
    for (int a = 0; a < 4; a++)
#pragma unroll
        for (int b = 0; b < 4; b++)
#pragma unroll
            for (int c = 0; c < 4; c++) acc[a][b][c] = 0.f;

    uint32_t aRow[4], aX[4], bRow[2], bX[2];
    uint32_t koffA = ((lane >> 4) & 1) * 16;
    uint32_t koffB = ((lane >> 3) & 1) * 16;
#pragma unroll
    for (int i = 0; i < 4; i++) {
        uint32_t ra = wm + i * 16 + (lane & 15);
        aRow[i] = ra * 128u; aX[i] = (ra & 7u) << 4;
    }
#pragma unroll
    for (int p = 0; p < 2; p++) {
        uint32_t rb = wn + p * 16 + ((lane >> 4) * 8) + (lane & 7);
        bRow[p] = rb * 128u; bX[p] = (rb & 7u) << 4;
    }

    const int KT = D_MODEL / 64;
    LOAD_STAGE(0, 0); CP_COMMIT();
    LOAD_STAGE(1, 1); CP_COMMIT();

    int s = 0;
    for (int j = 0; j < KT; j++) {
        CP_WAIT(1);
        __syncthreads();
        int jn = j + 2;
        int sl = s + 2; if (sl >= STAGES) sl -= STAGES;
        if (jn < KT) LOAD_STAGE(sl, jn);   // overwrites stage consumed at j-1
        CP_COMMIT();

        uint32_t aB = stg + (uint32_t)s * STAGE_BYTES;
        uint32_t bB = aB + 16384u;
#pragma unroll
        for (int kk = 0; kk < 4; kk++) {
            uint32_t kb = kk * 32u;
            uint32_t bfr[2][4];
#pragma unroll
            for (int p = 0; p < 2; p++)
                ldsm4(bfr[p], bB + bRow[p] + ((kb + koffB) ^ bX[p]));
#pragma unroll
            for (int mi = 0; mi < 4; mi++) {
                uint32_t afr[4];
                ldsm4(afr, aB + aRow[mi] + ((kb + koffA) ^ aX[mi]));
#pragma unroll
                for (int ni = 0; ni < 4; ni++)
                    mma16816(acc[mi][ni], afr, &bfr[ni >> 1][(ni & 1) * 2]);
            }
        }
        if (++s == STAGES) s = 0;
    }
    CP_WAIT(0);

    int g = lane >> 2, t4 = lane & 3;
    if (last) {
#pragma unroll
        for (int mi = 0; mi < 4; mi++) {
            size_t r0 = (size_t)(m0 + wm + mi * 16 + g);
#pragma unroll
            for (int ni = 0; ni < 4; ni++) {
                uint32_t col = n0 + wn + ni * 8 + t4 * 2;
                *(float2*)(dout + r0 * D_MODEL + col)       = make_float2(acc[mi][ni][0], acc[mi][ni][1]);
                *(float2*)(dout + (r0 + 8) * D_MODEL + col) = make_float2(acc[mi][ni][2], acc[mi][ni][3]);
            }
        }
    } else {
#pragma unroll
        for (int mi = 0; mi < 4; mi++) {
            size_t r0 = (size_t)(m0 + wm + mi * 16 + g);
#pragma unroll
            for (int ni = 0; ni < 4; ni++) {
                uint32_t col = n0 + wn + ni * 8 + t4 * 2;
                *(__half2*)(g_yh + r0 * D_MODEL + col)       = __floats2half2_rn(acc[mi][ni][0], acc[mi][ni][1]);
                *(__half2*)(g_yh + (r0 + 8) * D_MODEL + col) = __floats2half2_rn(acc[mi][ni][2], acc[mi][ni][3]);
            }
        }
    }
}

extern "C" void kernel_launch(void* const* d_in, const int* in_sizes, int n_in,
                              void* d_out, int out_size) {
    const float* x  = (const float*)d_in[0];
    const float* w0 = (const float*)d_in[1];
    const float* w1 = (const float*)d_in[2];
    const float* w2 = (const float*)d_in[3];
    cudaFuncSetAttribute(gemm_kernel, cudaFuncAttributeMaxDynamicSharedMemorySize, SMEM_TOTAL);
    absmean_part3<<<3072, 256>>>(w0, w1, w2);
    absmean_fin3<<<3, 256>>>();
    quant3<<<6144, 256>>>(w0, w1, w2);
    for (int l = 0; l < 3; l++) {
        act_kernel<<<N_TOK, 256>>>(x, l == 0);
        gemm_kernel<<<2048, 256, SMEM_TOTAL>>>(l, l == 2, (float*)d_out);
    }
}